// round 16
// baseline (speedup 1.0000x reference)
#include <cuda_runtime.h>
#include <mma.h>
#include <cstdint>
#include <cstddef>
#include <float.h>

namespace wm = nvcuda::wmma;

// ---------------- problem constants ----------------
constexpr int B   = 8;
constexpr int N0  = 8192;
constexpr int CX  = 24;
constexpr int S1  = 1024, K1 = 16;
constexpr int S2  = 512,  K2 = 32;

// ---------------- scratch ----------------
__device__ float  g_xt    [B * N0 * CX];
__device__ float4 g_l0xyz4[B * N0];
__device__ float4 g_l1xyz4[B * S1];
__device__ float4 g_l2xyz4[B * S2];
__device__ int    g_ball1 [B * S1 * K1];
__device__ float  g_l1p   [B * S1 * 128];
__device__ int    g_ball2 [B * S2 * K2];
__device__ float  g_l2p   [B * S2 * 256];
__device__ int    g_nn2i  [B * S1 * 3];
__device__ float  g_nn2w  [B * S1 * 3];
__device__ float  g_l1p2  [B * S1 * 256];
__device__ int    g_nn1i  [B * N0 * 3];
__device__ float  g_nn1w  [B * N0 * 3];
__device__ float  g_wt    [379648];

constexpr int OFF_SA1_0 = 0;        // 28 x 64
constexpr int OFF_SA1_1 = 1792;     // 64 x 128
constexpr int OFF_SA1_2 = 9984;     // 128 x 128
constexpr int OFF_SA2_0 = 26368;    // 136 x 128 (K padded 132->136 for wmma)
constexpr int OFF_SA2_1 = 43776;    // 128 x 256
constexpr int OFF_FP2_0 = 76544;    // 384 x 256
constexpr int OFF_FP2_1 = 174848;   // 256 x 256
constexpr int OFF_FP1_0 = 240384;   // 288 x 256 (K padded 284->288)
constexpr int OFF_FP1_1 = 314112;   // 256 x 256
constexpr int TOTAL_W   = 379648;

// ---------------- numeric helpers (pinned op order) ----------------
__device__ __forceinline__ float sumsq3(float x, float y, float z) {
    return fmaf(z, z, fmaf(y, y, __fmul_rn(x, x)));
}
__device__ __forceinline__ float sqdist_pre(float sc, float cx, float cy, float cz,
                                            float px, float py, float pz, float sp) {
    float dot = fmaf(cz, pz, fmaf(cy, py, __fmul_rn(cx, px)));
    return __fsub_rn(__fadd_rn(sc, sp), __fmul_rn(2.0f, dot));
}
__device__ __forceinline__ void top3_insert(float d, int p,
                                            float& D0, float& D1, float& D2,
                                            int& I0, int& I1, int& I2) {
    if (d < D2 || (d == D2 && p < I2)) {
        if (d < D1 || (d == D1 && p < I1)) {
            D2 = D1; I2 = I1;
            if (d < D0 || (d == D0 && p < I0)) { D1 = D0; I1 = I0; D0 = d; I0 = p; }
            else                               { D1 = d;  I1 = p; }
        } else { D2 = d; I2 = p; }
    }
}
__device__ __forceinline__ void warp_argmax(float& v, int& i) {
    unsigned vb = __float_as_uint(v);
    unsigned m  = __reduce_max_sync(0xffffffffu, vb);
    unsigned ci = (vb == m) ? (unsigned)i : 0xffffffffu;
    unsigned bi = __reduce_min_sync(0xffffffffu, ci);
    v = __uint_as_float(m);
    i = (int)bi;
}

// ---------------- scalar GEMM microkernel (sa1 only) ----------------
template <int NR>
__device__ __forceinline__ void mm4(const float* __restrict__ wt, int O, int og, int KP,
                                    const float* __restrict__ in0, int ld, float (&acc)[NR][4]) {
    const float4* wt4 = reinterpret_cast<const float4*>(wt);
    const int OV4 = O >> 2;
#pragma unroll 2
    for (int k = 0; k < KP; k += 4) {
        float4 wa = wt4[(k + 0) * OV4 + og];
        float4 wb = wt4[(k + 1) * OV4 + og];
        float4 wc = wt4[(k + 2) * OV4 + og];
        float4 wd = wt4[(k + 3) * OV4 + og];
#pragma unroll
        for (int r = 0; r < NR; r++) {
            const float4 gv = *reinterpret_cast<const float4*>(in0 + r * ld + k);
            acc[r][0] += gv.x * wa.x; acc[r][0] += gv.y * wb.x; acc[r][0] += gv.z * wc.x; acc[r][0] += gv.w * wd.x;
            acc[r][1] += gv.x * wa.y; acc[r][1] += gv.y * wb.y; acc[r][1] += gv.z * wc.y; acc[r][1] += gv.w * wd.y;
            acc[r][2] += gv.x * wa.z; acc[r][2] += gv.y * wb.z; acc[r][2] += gv.z * wc.z; acc[r][2] += gv.w * wd.z;
            acc[r][3] += gv.x * wa.w; acc[r][3] += gv.y * wb.w; acc[r][3] += gv.z * wc.w; acc[r][3] += gv.w * wd.w;
        }
    }
}

// ---------------- wmma tf32 single-pass GEMMs ----------------
using AFrag = wm::fragment<wm::matrix_a, 16, 16, 8, wm::precision::tf32, wm::row_major>;
using BFrag = wm::fragment<wm::matrix_b, 16, 16, 8, wm::precision::tf32, wm::row_major>;
using CFrag = wm::fragment<wm::accumulator, 16, 16, 8, float>;

// C[32][256] = A[32][K] * W[K][256]; 8 warps, C ld=256.
template <int KT8, int LDA>
__device__ void gemm_tf32_1p(const float* __restrict__ A,
                             const float* __restrict__ W,
                             float* __restrict__ C) {
    int w = threadIdx.x >> 5;
    CFrag acc[2][2];
#pragma unroll
    for (int mt = 0; mt < 2; mt++)
#pragma unroll
        for (int j = 0; j < 2; j++) wm::fill_fragment(acc[mt][j], 0.0f);
    for (int kt = 0; kt < KT8; kt++) {
        BFrag bf[2];
#pragma unroll
        for (int j = 0; j < 2; j++) {
            wm::load_matrix_sync(bf[j], W + (size_t)kt * 8 * 256 + (w * 2 + j) * 16, 256);
#pragma unroll
            for (int i = 0; i < bf[j].num_elements; i++)
                bf[j].x[i] = wm::__float_to_tf32(bf[j].x[i]);
        }
#pragma unroll
        for (int mt = 0; mt < 2; mt++) {
            AFrag af;
            wm::load_matrix_sync(af, A + mt * 16 * LDA + kt * 8, LDA);
#pragma unroll
            for (int i = 0; i < af.num_elements; i++)
                af.x[i] = wm::__float_to_tf32(af.x[i]);
#pragma unroll
            for (int j = 0; j < 2; j++)
                wm::mma_sync(acc[mt][j], af, bf[j], acc[mt][j]);
        }
    }
#pragma unroll
    for (int mt = 0; mt < 2; mt++)
#pragma unroll
        for (int j = 0; j < 2; j++)
            wm::store_matrix_sync(C + mt * 16 * 256 + (w * 2 + j) * 16, acc[mt][j],
                                  256, wm::mem_row_major);
}

// C[32][128] = A[32][K] * W[K][128]; 8 warps (one 16-col tile each), C ld=128.
template <int KT8, int LDA>
__device__ void gemm_tf32_32x128(const float* __restrict__ A,
                                 const float* __restrict__ W,
                                 float* __restrict__ C) {
    int w = threadIdx.x >> 5;
    CFrag acc[2];
#pragma unroll
    for (int mt = 0; mt < 2; mt++) wm::fill_fragment(acc[mt], 0.0f);
    for (int kt = 0; kt < KT8; kt++) {
        BFrag bf;
        wm::load_matrix_sync(bf, W + (size_t)kt * 8 * 128 + w * 16, 128);
#pragma unroll
        for (int i = 0; i < bf.num_elements; i++)
            bf.x[i] = wm::__float_to_tf32(bf.x[i]);
#pragma unroll
        for (int mt = 0; mt < 2; mt++) {
            AFrag af;
            wm::load_matrix_sync(af, A + mt * 16 * LDA + kt * 8, LDA);
#pragma unroll
            for (int i = 0; i < af.num_elements; i++)
                af.x[i] = wm::__float_to_tf32(af.x[i]);
            wm::mma_sync(acc[mt], af, bf, acc[mt]);
        }
    }
#pragma unroll
    for (int mt = 0; mt < 2; mt++)
        wm::store_matrix_sync(C + mt * 16 * 128 + w * 16, acc[mt], 128, wm::mem_row_major);
}

// C16[16][256] = rowpair-max of A[32][K] * W[K][256].
template <int KT8, int LDA>
__device__ void gemm_tf32_32x256_maxpair(const float* __restrict__ A,
                                         const float* __restrict__ W,
                                         float* __restrict__ C16) {
    int w = threadIdx.x >> 5;
    CFrag acc[2][2];
#pragma unroll
    for (int mt = 0; mt < 2; mt++)
#pragma unroll
        for (int j = 0; j < 2; j++) wm::fill_fragment(acc[mt][j], 0.0f);
    for (int kt = 0; kt < KT8; kt++) {
        BFrag bf[2];
#pragma unroll
        for (int j = 0; j < 2; j++) {
            wm::load_matrix_sync(bf[j], W + (size_t)kt * 8 * 256 + (w * 2 + j) * 16, 256);
#pragma unroll
            for (int i = 0; i < bf[j].num_elements; i++)
                bf[j].x[i] = wm::__float_to_tf32(bf[j].x[i]);
        }
#pragma unroll
        for (int mt = 0; mt < 2; mt++) {
            AFrag af;
            wm::load_matrix_sync(af, A + mt * 16 * LDA + kt * 8, LDA);
#pragma unroll
            for (int i = 0; i < af.num_elements; i++)
                af.x[i] = wm::__float_to_tf32(af.x[i]);
#pragma unroll
            for (int j = 0; j < 2; j++)
                wm::mma_sync(acc[mt][j], af, bf[j], acc[mt][j]);
        }
    }
#pragma unroll
    for (int j = 0; j < 2; j++) {
#pragma unroll
        for (int i = 0; i < acc[0][j].num_elements; i++)
            acc[0][j].x[i] = fmaxf(acc[0][j].x[i], acc[1][j].x[i]);
        wm::store_matrix_sync(C16 + (w * 2 + j) * 16, acc[0][j], 256, wm::mem_row_major);
    }
}

// ---------------- prep: blocks 0..7 = FPS over raw xyz; rest = transposes ----------------
struct WT9 {
    const float* W[9];
    int off[9], O[9], K[9], Kpad[9];
};
__global__ void __launch_bounds__(1024) prep_kernel(const float* __restrict__ xyz, WT9 w) {
    __shared__ int   s_far;
    __shared__ float s_v[32];
    __shared__ int   s_i[32];
    int tid = threadIdx.x;
    if (blockIdx.x < B) {
        int b = blockIdx.x;
        const float* base = xyz + (size_t)b * CX * N0;
        float px[8], py[8], pz[8], dist[8];
#pragma unroll
        for (int j = 0; j < 8; j++) {
            int p = tid + j * 1024;
            px[j] = base[p];
            py[j] = base[p + N0];
            pz[j] = base[p + 2 * N0];
            dist[j] = 1e10f;
        }
        float4* out4 = g_l1xyz4 + (size_t)b * S1;
        if (tid == 0) s_far = 0;
        __syncthreads();
        for (int it = 0; it < S1; it++) {
            int far = s_far;
            float cx = base[far], cy = base[far + N0], cz = base[far + 2 * N0];
            if (tid == 0) out4[it] = make_float4(cx, cy, cz, sumsq3(cx, cy, cz));
            float bv = -1.0f; int bj = 0;
#pragma unroll
            for (int j = 0; j < 8; j++) {
                float dx = __fsub_rn(px[j], cx);
                float dy = __fsub_rn(py[j], cy);
                float dz = __fsub_rn(pz[j], cz);
                float d = fmaf(dz, dz, fmaf(dy, dy, __fmul_rn(dx, dx)));
                float nd = fminf(dist[j], d);
                dist[j] = nd;
                if (nd > bv) { bv = nd; bj = j; }
            }
            int bi = tid + bj * 1024;
            warp_argmax(bv, bi);
            if ((tid & 31) == 0) { s_v[tid >> 5] = bv; s_i[tid >> 5] = bi; }
            __syncthreads();
            if (tid < 32) {
                bv = s_v[tid]; bi = s_i[tid];
                warp_argmax(bv, bi);
                if (tid == 0) s_far = bi;
            }
            __syncthreads();
        }
        return;
    }
    int i = (blockIdx.x - B) * 1024 + tid;
    if (i < B * N0) {
        int b = i >> 13, n = i & (N0 - 1);
        const float* src = xyz + (size_t)b * CX * N0 + n;
        float* dst = g_xt + (size_t)i * CX;
        float x = src[0], y = src[(size_t)N0], z = src[(size_t)2 * N0];
#pragma unroll
        for (int c = 0; c < CX; c++) dst[c] = src[(size_t)c * N0];
        g_l0xyz4[i] = make_float4(x, y, z, sumsq3(x, y, z));
        return;
    }
    i -= B * N0;
#pragma unroll
    for (int s = 0; s < 9; s++) {
        int n = w.Kpad[s] * w.O[s];
        if (i < n) {
            int k = i / w.O[s], o = i - k * w.O[s];
            g_wt[w.off[s] + i] = (k < w.K[s]) ? w.W[s][o * w.K[s] + k] : 0.0f;
            return;
        }
        i -= n;
    }
}

// ---------------- FPS body (float4 source) ----------------
template <int PPT, int NP>
__device__ __forceinline__ void fps_body4(const float4* __restrict__ base,
                                          float4* __restrict__ out4,
                                          int tid, int* s_far, float* s_v, int* s_i) {
    float px[PPT], py[PPT], pz[PPT], dist[PPT];
#pragma unroll
    for (int j = 0; j < PPT; j++) {
        float4 P = base[tid + j * 1024];
        px[j] = P.x; py[j] = P.y; pz[j] = P.z;
        dist[j] = 1e10f;
    }
    if (tid == 0) *s_far = 0;
    __syncthreads();
    for (int it = 0; it < NP; it++) {
        int far = *s_far;
        float4 C = base[far];
        float cx = C.x, cy = C.y, cz = C.z;
        if (tid == 0) out4[it] = make_float4(cx, cy, cz, sumsq3(cx, cy, cz));
        float bv = -1.0f; int bj = 0;
#pragma unroll
        for (int j = 0; j < PPT; j++) {
            float dx = __fsub_rn(px[j], cx);
            float dy = __fsub_rn(py[j], cy);
            float dz = __fsub_rn(pz[j], cz);
            float d = fmaf(dz, dz, fmaf(dy, dy, __fmul_rn(dx, dx)));
            float nd = fminf(dist[j], d);
            dist[j] = nd;
            if (nd > bv) { bv = nd; bj = j; }
        }
        int bi = tid + bj * 1024;
        warp_argmax(bv, bi);
        if ((tid & 31) == 0) { s_v[tid >> 5] = bv; s_i[tid >> 5] = bi; }
        __syncthreads();
        if (tid < 32) {
            bv = s_v[tid]; bi = s_i[tid];
            warp_argmax(bv, bi);
            if (tid == 0) *s_far = bi;
        }
        __syncthreads();
    }
}

// ---------------- warp ball-query body ----------------
__device__ __forceinline__ void ball_body(const float4* __restrict__ centers,
                                          const float4* __restrict__ pts4,
                                          int nptsB, int SQ, float r2, int nsample,
                                          int* __restrict__ out, int gw, int lane,
                                          int* __restrict__ buf) {
    int b = gw / SQ;
    float4 C = centers[gw];
    float cx = C.x, cy = C.y, cz = C.z, sc = C.w;
    const float4* pb = pts4 + (size_t)b * nptsB;
    int kept = 0;
    for (int j0 = 0; j0 < nptsB; j0 += 32) {
        int p = j0 + lane;
        float4 P = pb[p];
        float d = sqdist_pre(sc, cx, cy, cz, P.x, P.y, P.z, P.w);
        bool in = !(d > r2);
        unsigned m = __ballot_sync(0xffffffffu, in);
        int rank = kept + __popc(m & ((1u << lane) - 1u));
        if (in && rank < nsample) buf[rank] = p;
        kept += __popc(m);
        if (kept >= nsample) break;
    }
    __syncwarp();
    int first = buf[0];
    for (int i = lane; i < nsample; i += 32)
        out[(size_t)gw * nsample + i] = (i < kept) ? buf[i] : first;
}

// ---------------- warp 3-NN body ----------------
__device__ __forceinline__ void nn3_body(const float4* __restrict__ qpts4,
                                         const float4* __restrict__ pts4,
                                         int nptsB, int SQ,
                                         int* __restrict__ oi, float* __restrict__ ow,
                                         int gw, int lane) {
    int b = gw / SQ;
    float4 Q = qpts4[gw];
    float cx = Q.x, cy = Q.y, cz = Q.z, sc = Q.w;
    const float4* pb = pts4 + (size_t)b * nptsB;
    float D0 = FLT_MAX, D1 = FLT_MAX, D2 = FLT_MAX;
    int   I0 = 0x7fffffff, I1 = 0x7fffffff, I2 = 0x7fffffff;
    for (int p = lane; p < nptsB; p += 32) {
        float4 P = pb[p];
        float d = sqdist_pre(sc, cx, cy, cz, P.x, P.y, P.z, P.w);
        top3_insert(d, p, D0, D1, D2, I0, I1, I2);
    }
    for (int off = 16; off; off >>= 1) {
        float e0 = __shfl_down_sync(0xffffffffu, D0, off);
        float e1 = __shfl_down_sync(0xffffffffu, D1, off);
        float e2 = __shfl_down_sync(0xffffffffu, D2, off);
        int   f0 = __shfl_down_sync(0xffffffffu, I0, off);
        int   f1 = __shfl_down_sync(0xffffffffu, I1, off);
        int   f2 = __shfl_down_sync(0xffffffffu, I2, off);
        top3_insert(e0, f0, D0, D1, D2, I0, I1, I2);
        top3_insert(e1, f1, D0, D1, D2, I0, I1, I2);
        top3_insert(e2, f2, D0, D1, D2, I0, I1, I2);
    }
    if (lane == 0) {
        float r0 = 1.0f / (D0 + 1e-8f);
        float r1 = 1.0f / (D1 + 1e-8f);
        float r2 = 1.0f / (D2 + 1e-8f);
        float s = (r0 + r1) + r2;
        oi[(size_t)gw * 3 + 0] = I0; oi[(size_t)gw * 3 + 1] = I1; oi[(size_t)gw * 3 + 2] = I2;
        ow[(size_t)gw * 3 + 0] = r0 / s; ow[(size_t)gw * 3 + 1] = r1 / s; ow[(size_t)gw * 3 + 2] = r2 / s;
    }
}

// ---------------- M1: fps1 (0..7) + ball1 (8..263) + nn1 (264..2311) ----------------
constexpr int M1_BALL1 = 256;
constexpr int M1_NN1   = 2048;
constexpr int M1_GRID  = B + M1_BALL1 + M1_NN1;

__global__ void __launch_bounds__(1024) m1_kernel(float r2_1) {
    __shared__ int   sbuf[32][32];
    __shared__ int   s_far;
    __shared__ float s_v[32];
    __shared__ int   s_i[32];
    if (blockIdx.x < B) {
        fps_body4<1, S2>(g_l1xyz4 + (size_t)blockIdx.x * S1,
                         g_l2xyz4 + (size_t)blockIdx.x * S2,
                         threadIdx.x, &s_far, s_v, s_i);
    } else if (blockIdx.x < B + M1_BALL1) {
        int wl = threadIdx.x >> 5, lane = threadIdx.x & 31;
        int gw = (blockIdx.x - B) * 32 + wl;
        ball_body(g_l1xyz4, g_l0xyz4, N0, S1, r2_1, K1, g_ball1, gw, lane, &sbuf[wl][0]);
    } else {
        int wl = threadIdx.x >> 5, lane = threadIdx.x & 31;
        int gw = (blockIdx.x - B - M1_BALL1) * 32 + wl;
        nn3_body(g_l0xyz4, g_l1xyz4, S1, N0, g_nn1i, g_nn1w, gw, lane);
    }
}

// ---------------- M2: sa1 (4 queries/block, 256 thr, dynamic smem) + ball2 + nn2 ----------------
constexpr int M2_SA1   = 2048;   // 8192 queries / 4
constexpr int M2_BALL2 = 512;    // 4096 queries / 8 warps
constexpr int M2_NN2   = 1024;   // 8192 queries / 8 warps
constexpr int M2_GRID  = M2_SA1 + M2_BALL2 + M2_NN2;
// dynamic: g[64][28] + h1s[64][64] + h2s[64][128] + pmax[8][128]
constexpr int M2_SMEM  = (64 * 28 + 64 * 64 + 64 * 128 + 8 * 128) * 4;   // 60416 B

__global__ void __launch_bounds__(256) m2_kernel(const float* __restrict__ b0,
                                                 const float* __restrict__ b1,
                                                 const float* __restrict__ b2,
                                                 float r2_2) {
    extern __shared__ float md[];
    float* g    = md;                                  // [64][28]
    float* h1s  = md + 64 * 28;                        // [64][64]
    float* h2s  = md + 64 * 28 + 64 * 64;              // [64][128]
    float* pmax = md + 64 * 28 + 64 * 64 + 64 * 128;   // [8][128]
    __shared__ int   sidx[64];
    __shared__ float ctr[4][4];
    __shared__ int   sbuf[8][32];
    int bid = blockIdx.x;
    int tid = threadIdx.x;
    int wl = tid >> 5, lane = tid & 31;

    if (bid >= M2_SA1) {
        int r = bid - M2_SA1;
        if (r < M2_BALL2) {
            int gw = r * 8 + wl;                          // 0..4095
            ball_body(g_l2xyz4, g_l1xyz4, S1, S2, r2_2, K2, g_ball2, gw, lane, &sbuf[wl][0]);
        } else {
            int gw = (r - M2_BALL2) * 8 + wl;             // 0..8191
            nn3_body(g_l1xyz4, g_l2xyz4, S2, S1, g_nn2i, g_nn2w, gw, lane);
        }
        return;
    }

    // ---- sa1: queries q0..q0+3; rows r -> query r>>4 ----
    int q0 = bid * 4;
    int b = q0 >> 10;
    if (tid < 64) sidx[tid] = g_ball1[q0 * 16 + tid];
    if (tid >= 64 && tid < 80) ((float*)ctr)[tid - 64] = ((const float*)&g_l1xyz4[q0])[tid - 64];
    __syncthreads();
    for (int e = tid; e < 64 * 28; e += 256) {
        int r = e / 28, c = e - r * 28;
        float v = 0.0f;
        if (c < 27) {
            const float* row = g_xt + ((size_t)(b * N0 + sidx[r])) * CX;
            v = (c < 3) ? (row[c] - ctr[r >> 4][c]) : row[c - 3];
        }
        g[r * 28 + c] = v;
    }
    __syncthreads();
    {   // layer1: K=28, O=64; 16 og x 16 rg (4 rows)
        int og = tid & 15, rg = tid >> 4, o0 = og * 4;
        float acc[4][4];
#pragma unroll
        for (int r = 0; r < 4; r++)
#pragma unroll
            for (int j = 0; j < 4; j++) acc[r][j] = b0[o0 + j];
        mm4<4>(g_wt + OFF_SA1_0, 64, og, 28, g + rg * 4 * 28, 28, acc);
#pragma unroll
        for (int r = 0; r < 4; r++)
#pragma unroll
            for (int j = 0; j < 4; j++) h1s[(rg * 4 + r) * 64 + o0 + j] = fmaxf(acc[r][j], 0.0f);
    }
    __syncthreads();
    {   // layer2: K=64, O=128; 32 og x 8 rg (8 rows)
        int og = tid & 31, rg = tid >> 5, o0 = og * 4;
        float acc[8][4];
#pragma unroll
        for (int r = 0; r < 8; r++)
#pragma unroll
            for (int j = 0; j < 4; j++) acc[r][j] = b1[o0 + j];
        mm4<8>(g_wt + OFF_SA1_1, 128, og, 64, h1s + rg * 8 * 64, 64, acc);
#pragma unroll
        for (int r = 0; r < 8; r++)
#pragma unroll
            for (int j = 0; j < 4; j++) h2s[(rg * 8 + r) * 128 + o0 + j] = fmaxf(acc[r][j], 0.0f);
    }
    __syncthreads();
    {   // layer3: K=128, O=128; 32 og x 8 rg (8 rows; each group within one query half)
        int og = tid & 31, rg = tid >> 5, o0 = og * 4;
        float acc[8][4];
#pragma unroll
        for (int r = 0; r < 8; r++)
#pragma unroll
            for (int j = 0; j < 4; j++) acc[r][j] = 0.0f;
        mm4<8>(g_wt + OFF_SA1_2, 128, og, 128, h2s + rg * 8 * 128, 128, acc);
#pragma unroll
        for (int j = 0; j < 4; j++) {
            float m = acc[0][j];
#pragma unroll
            for (int r = 1; r < 8; r++) m = fmaxf(m, acc[r][j]);
            pmax[rg * 128 + o0 + j] = m;
        }
    }
    __syncthreads();
    {   // combine: query qi = groups 2qi, 2qi+1
#pragma unroll
        for (int pass = 0; pass < 2; pass++) {
            int qi = pass * 2 + (tid >> 7);
            int o = tid & 127;
            float m = fmaxf(pmax[2 * qi * 128 + o], pmax[(2 * qi + 1) * 128 + o]);
            g_l1p[(size_t)(q0 + qi) * 128 + o] = fmaxf(m + b2[o], 0.0f);
        }
    }
}

// ---------------- SA2 (wmma tf32): 256 threads, c16 aliased onto g ----------------
constexpr int SA2_SMEM = (32 * 136 + 32 * 128) * 4;   // 33792 B (c16 aliases g)

__global__ void __launch_bounds__(256, 4) sa2_kernel(const float* __restrict__ b0,
                                                     const float* __restrict__ b1) {
    extern __shared__ float sd[];
    float* g   = sd;                 // [32][136] (cols 131..135 zero)
    float* h1s = sd + 32 * 136;      // [32][128]
    float* c16 = sd;                 // [16][256] aliases g (g dead after layer1 gemm)
    __shared__ int   sidx[32];
    __shared__ float ctr[3];
    int tid = threadIdx.x;

    int q = blockIdx.x;
    int b = q >> 9;
    if (tid < 32) sidx[tid] = g_ball2[q * 32 + tid];
    if (tid >= 32 && tid < 35) ctr[tid - 32] = ((const float*)&g_l2xyz4[q])[tid - 32];
    __syncthreads();
    for (int e = tid; e < 32 * 136; e += 256) {
        int r = e / 136, c = e - r * 136;
        float v = 0.0f;
        if (c < 131) {
            int p = sidx[r];
            if (c < 3) v = ((const float*)&g_l1xyz4[(size_t)b * S1 + p])[c] - ctr[c];
            else       v = g_l1p[((size_t)b * S1 + p) * 128 + (c - 3)];
        }
        g[r * 136 + c] = v;
    }
    __syncthreads();
    gemm_tf32_32x128<17, 136>(g, g_wt + OFF_SA2_0, h1s);
    __syncthreads();
    for (int e = tid; e < 32 * 128; e += 256)
        h1s[e] = fmaxf(h1s[e] + b0[e & 127], 0.0f);
    __syncthreads();   // g fully dead after this point; c16 may now overwrite it
    gemm_tf32_32x256_maxpair<16, 128>(h1s, g_wt + OFF_SA2_1, c16);
    __syncthreads();
    {
        int o = tid;
        float m = c16[o];
#pragma unroll
        for (int r = 1; r < 16; r++) m = fmaxf(m, c16[r * 256 + o]);
        g_l2p[(size_t)q * 256 + o] = fmaxf(m + b1[o], 0.0f);
    }
}

// ---------------- FP2 (wmma tf32): interp + concat + MLP(384->256->256), 32 rows ----------------
constexpr int FP2_SMEM = (32 * 384 + 32 * 256) * 4;   // 81920 B

__global__ void __launch_bounds__(256) fp2_kernel(const float* __restrict__ b0,
                                                  const float* __restrict__ b1) {
    extern __shared__ float sd[];
    float* feat = sd;               // [32][384]
    float* h1s  = sd + 32 * 384;    // [32][256]
    __shared__ int   nni[32][3];
    __shared__ float nnw[32][3];
    int row0 = blockIdx.x * 32;
    int b = row0 >> 10;
    int tid = threadIdx.x;
    if (tid < 96)                    nni[tid / 3][tid % 3] = g_nn2i[(size_t)row0 * 3 + tid];
    else if (tid < 192) { int t = tid - 96; nnw[t / 3][t % 3] = g_nn2w[(size_t)row0 * 3 + t]; }
    for (int e = tid; e < 32 * 128; e += 256) {
        int r = e >> 7, c = e & 127;
        feat[r * 384 + c] = g_l1p[((size_t)row0 + r) * 128 + c];
    }
    __syncthreads();
    {
        const float* p2 = g_l2p + (size_t)b * S2 * 256;
        int c = tid;
#pragma unroll 4
        for (int r = 0; r < 32; r++) {
            float v = p2[(size_t)nni[r][0] * 256 + c] * nnw[r][0];
            v += p2[(size_t)nni[r][1] * 256 + c] * nnw[r][1];
            v += p2[(size_t)nni[r][2] * 256 + c] * nnw[r][2];
            feat[r * 384 + 128 + c] = v;
        }
    }
    __syncthreads();
    gemm_tf32_1p<48, 384>(feat, g_wt + OFF_FP2_0, h1s);
    __syncthreads();
    for (int e = tid; e < 32 * 256; e += 256)
        h1s[e] = fmaxf(h1s[e] + b0[e & 255], 0.0f);
    __syncthreads();
    gemm_tf32_1p<32, 256>(h1s, g_wt + OFF_FP2_1, feat);   // staging (ld 256)
    __syncthreads();
    for (int e = tid; e < 32 * 256; e += 256)
        g_l1p2[((size_t)row0 + (e >> 8)) * 256 + (e & 255)] = fmaxf(feat[e] + b1[e & 255], 0.0f);
}

// ---------------- FP1 (wmma tf32): concat + MLP(288pad->256->256) -> out ----------------
constexpr int FP1_SMEM = (32 * 288 + 32 * 256) * 4;

__global__ void __launch_bounds__(256) fp1_kernel(const float* __restrict__ b0,
                                                  const float* __restrict__ b1,
                                                  float* __restrict__ out) {
    extern __shared__ float sd[];
    float* feat = sd;               // [32][288], cols 283..287 zero
    float* h1s  = sd + 32 * 288;    // [32][256]
    __shared__ int   nni[32][3];
    __shared__ float nnw[32][3];
    int row0 = blockIdx.x * 32;
    int b = row0 >> 13;
    int tid = threadIdx.x;
    if (tid < 96)                    nni[tid / 3][tid % 3] = g_nn1i[(size_t)row0 * 3 + tid];
    else if (tid < 192) { int t = tid - 96; nnw[t / 3][t % 3] = g_nn1w[(size_t)row0 * 3 + t]; }
    for (int e = tid; e < 32 * 27; e += 256) {
        int r = e / 27, c = e - r * 27;
        const float* row = g_xt + (size_t)(row0 + r) * CX;
        feat[r * 288 + c] = (c < 3) ? row[c] : row[c - 3];
    }
    if (tid < 32) {
#pragma unroll
        for (int c = 283; c < 288; c++) feat[tid * 288 + c] = 0.0f;
    }
    __syncthreads();
    {
        const float* p1 = g_l1p2 + (size_t)b * S1 * 256;
        int c = tid;
#pragma unroll 4
        for (int r = 0; r < 32; r++) {
            float v = p1[(size_t)nni[r][0] * 256 + c] * nnw[r][0];
            v += p1[(size_t)nni[r][1] * 256 + c] * nnw[r][1];
            v += p1[(size_t)nni[r][2] * 256 + c] * nnw[r][2];
            feat[r * 288 + 27 + c] = v;
        }
    }
    __syncthreads();
    gemm_tf32_1p<36, 288>(feat, g_wt + OFF_FP1_0, h1s);
    __syncthreads();
    for (int e = tid; e < 32 * 256; e += 256)
        h1s[e] = fmaxf(h1s[e] + b0[e & 255], 0.0f);
    __syncthreads();
    gemm_tf32_1p<32, 256>(h1s, g_wt + OFF_FP1_1, feat);   // staging (ld 256)
    __syncthreads();
    for (int e = tid; e < 32 * 256; e += 256)
        out[((size_t)row0 + (e >> 8)) * 256 + (e & 255)] = fmaxf(feat[e] + b1[e & 255], 0.0f);
}

// ---------------- launch ----------------
extern "C" void kernel_launch(void* const* d_in, const int* in_sizes, int n_in,
                              void* d_out, int out_size) {
    const float* xyz = (const float*)d_in[0];
    const float* sa1_b0 = (const float*)d_in[2];
    const float* sa1_b1 = (const float*)d_in[4];
    const float* sa1_b2 = (const float*)d_in[6];
    const float* sa2_b0 = (const float*)d_in[8];
    const float* sa2_b1 = (const float*)d_in[10];
    const float* fp2_b0 = (const float*)d_in[12];
    const float* fp2_b1 = (const float*)d_in[14];
    const float* fp1_b0 = (const float*)d_in[16];
    const float* fp1_b1 = (const float*)d_in[18];
    float* out = (float*)d_out;

    const float r2_1 = (float)(0.035 * 0.035);
    const float r2_2 = (float)(0.0176 * 0.0176);

    WT9 w;
    const int offs[9]  = { OFF_SA1_0, OFF_SA1_1, OFF_SA1_2, OFF_SA2_0, OFF_SA2_1,
                           OFF_FP2_0, OFF_FP2_1, OFF_FP1_0, OFF_FP1_1 };
    const int Os[9]    = { 64, 128, 128, 128, 256, 256, 256, 256, 256 };
    const int Ks[9]    = { 27, 64, 128, 131, 128, 384, 256, 283, 256 };
    const int Kpads[9] = { 28, 64, 128, 136, 128, 384, 256, 288, 256 };
    const int widx[9]  = { 1, 3, 5, 7, 9, 11, 13, 15, 17 };
    for (int i = 0; i < 9; i++) {
        w.W[i] = (const float*)d_in[widx[i]];
        w.off[i] = offs[i]; w.O[i] = Os[i]; w.K[i] = Ks[i]; w.Kpad[i] = Kpads[i];
    }
    int prep_grid = B + (B * N0 + TOTAL_W + 1023) / 1024;
    prep_kernel<<<prep_grid, 1024>>>(xyz, w);

    m1_kernel<<<M1_GRID, 1024>>>(r2_1);

    cudaFuncSetAttribute(m2_kernel, cudaFuncAttributeMaxDynamicSharedMemorySize, M2_SMEM);
    m2_kernel<<<M2_GRID, 256, M2_SMEM>>>(sa1_b0, sa1_b1, sa1_b2, r2_2);

    cudaFuncSetAttribute(sa2_kernel, cudaFuncAttributeMaxDynamicSharedMemorySize, SA2_SMEM);
    sa2_kernel<<<B * S2, 256, SA2_SMEM>>>(sa2_b0, sa2_b1);

    cudaFuncSetAttribute(fp2_kernel, cudaFuncAttributeMaxDynamicSharedMemorySize, FP2_SMEM);
    fp2_kernel<<<B * S1 / 32, 256, FP2_SMEM>>>(fp2_b0, fp2_b1);

    cudaFuncSetAttribute(fp1_kernel, cudaFuncAttributeMaxDynamicSharedMemorySize, FP1_SMEM);
    fp1_kernel<<<B * N0 / 32, 256, FP1_SMEM>>>(fp1_b0, fp1_b1, out);
}

// round 17
// speedup vs baseline: 1.0154x; 1.0154x over previous
#include <cuda_runtime.h>
#include <mma.h>
#include <cstdint>
#include <cstddef>
#include <float.h>

namespace wm = nvcuda::wmma;

// ---------------- problem constants ----------------
constexpr int B   = 8;
constexpr int N0  = 8192;
constexpr int CX  = 24;
constexpr int S1  = 1024, K1 = 16;
constexpr int S2  = 512,  K2 = 32;

// ---------------- scratch ----------------
__device__ float  g_xt    [B * N0 * CX];
__device__ float4 g_l0xyz4[B * N0];
__device__ float4 g_l1xyz4[B * S1];
__device__ float4 g_l2xyz4[B * S2];
__device__ int    g_ball1 [B * S1 * K1];
__device__ float  g_l1p   [B * S1 * 128];
__device__ int    g_ball2 [B * S2 * K2];
__device__ float  g_l2p   [B * S2 * 256];
__device__ int    g_nn2i  [B * S1 * 3];
__device__ float  g_nn2w  [B * S1 * 3];
__device__ float  g_l1p2  [B * S1 * 256];
__device__ int    g_nn1i  [B * N0 * 3];
__device__ float  g_nn1w  [B * N0 * 3];
__device__ float  g_wt    [379648];

constexpr int OFF_SA1_0 = 0;        // 28 x 64
constexpr int OFF_SA1_1 = 1792;     // 64 x 128
constexpr int OFF_SA1_2 = 9984;     // 128 x 128
constexpr int OFF_SA2_0 = 26368;    // 136 x 128 (K padded 132->136 for wmma)
constexpr int OFF_SA2_1 = 43776;    // 128 x 256
constexpr int OFF_FP2_0 = 76544;    // 384 x 256
constexpr int OFF_FP2_1 = 174848;   // 256 x 256
constexpr int OFF_FP1_0 = 240384;   // 288 x 256 (K padded 284->288)
constexpr int OFF_FP1_1 = 314112;   // 256 x 256
constexpr int TOTAL_W   = 379648;

// ---------------- numeric helpers (pinned op order) ----------------
__device__ __forceinline__ float sumsq3(float x, float y, float z) {
    return fmaf(z, z, fmaf(y, y, __fmul_rn(x, x)));
}
__device__ __forceinline__ float sqdist_pre(float sc, float cx, float cy, float cz,
                                            float px, float py, float pz, float sp) {
    float dot = fmaf(cz, pz, fmaf(cy, py, __fmul_rn(cx, px)));
    return __fsub_rn(__fadd_rn(sc, sp), __fmul_rn(2.0f, dot));
}
__device__ __forceinline__ void top3_insert(float d, int p,
                                            float& D0, float& D1, float& D2,
                                            int& I0, int& I1, int& I2) {
    if (d < D2 || (d == D2 && p < I2)) {
        if (d < D1 || (d == D1 && p < I1)) {
            D2 = D1; I2 = I1;
            if (d < D0 || (d == D0 && p < I0)) { D1 = D0; I1 = I0; D0 = d; I0 = p; }
            else                               { D1 = d;  I1 = p; }
        } else { D2 = d; I2 = p; }
    }
}
__device__ __forceinline__ void warp_argmax(float& v, int& i) {
    unsigned vb = __float_as_uint(v);
    unsigned m  = __reduce_max_sync(0xffffffffu, vb);
    unsigned ci = (vb == m) ? (unsigned)i : 0xffffffffu;
    unsigned bi = __reduce_min_sync(0xffffffffu, ci);
    v = __uint_as_float(m);
    i = (int)bi;
}

// ---------------- scalar GEMM microkernel (sa1 only) ----------------
template <int NR>
__device__ __forceinline__ void mm4(const float* __restrict__ wt, int O, int og, int KP,
                                    const float* __restrict__ in0, int ld, float (&acc)[NR][4]) {
    const float4* wt4 = reinterpret_cast<const float4*>(wt);
    const int OV4 = O >> 2;
#pragma unroll 2
    for (int k = 0; k < KP; k += 4) {
        float4 wa = wt4[(k + 0) * OV4 + og];
        float4 wb = wt4[(k + 1) * OV4 + og];
        float4 wc = wt4[(k + 2) * OV4 + og];
        float4 wd = wt4[(k + 3) * OV4 + og];
#pragma unroll
        for (int r = 0; r < NR; r++) {
            const float4 gv = *reinterpret_cast<const float4*>(in0 + r * ld + k);
            acc[r][0] += gv.x * wa.x; acc[r][0] += gv.y * wb.x; acc[r][0] += gv.z * wc.x; acc[r][0] += gv.w * wd.x;
            acc[r][1] += gv.x * wa.y; acc[r][1] += gv.y * wb.y; acc[r][1] += gv.z * wc.y; acc[r][1] += gv.w * wd.y;
            acc[r][2] += gv.x * wa.z; acc[r][2] += gv.y * wb.z; acc[r][2] += gv.z * wc.z; acc[r][2] += gv.w * wd.z;
            acc[r][3] += gv.x * wa.w; acc[r][3] += gv.y * wb.w; acc[r][3] += gv.z * wc.w; acc[r][3] += gv.w * wd.w;
        }
    }
}

// ---------------- wmma tf32 single-pass GEMMs ----------------
using AFrag = wm::fragment<wm::matrix_a, 16, 16, 8, wm::precision::tf32, wm::row_major>;
using BFrag = wm::fragment<wm::matrix_b, 16, 16, 8, wm::precision::tf32, wm::row_major>;
using CFrag = wm::fragment<wm::accumulator, 16, 16, 8, float>;

// C[32][256] = A[32][K] * W[K][256]; 8 warps, C ld=256.
template <int KT8, int LDA>
__device__ void gemm_tf32_1p(const float* __restrict__ A,
                             const float* __restrict__ W,
                             float* __restrict__ C) {
    int w = threadIdx.x >> 5;
    CFrag acc[2][2];
#pragma unroll
    for (int mt = 0; mt < 2; mt++)
#pragma unroll
        for (int j = 0; j < 2; j++) wm::fill_fragment(acc[mt][j], 0.0f);
    for (int kt = 0; kt < KT8; kt++) {
        BFrag bf[2];
#pragma unroll
        for (int j = 0; j < 2; j++) {
            wm::load_matrix_sync(bf[j], W + (size_t)kt * 8 * 256 + (w * 2 + j) * 16, 256);
#pragma unroll
            for (int i = 0; i < bf[j].num_elements; i++)
                bf[j].x[i] = wm::__float_to_tf32(bf[j].x[i]);
        }
#pragma unroll
        for (int mt = 0; mt < 2; mt++) {
            AFrag af;
            wm::load_matrix_sync(af, A + mt * 16 * LDA + kt * 8, LDA);
#pragma unroll
            for (int i = 0; i < af.num_elements; i++)
                af.x[i] = wm::__float_to_tf32(af.x[i]);
#pragma unroll
            for (int j = 0; j < 2; j++)
                wm::mma_sync(acc[mt][j], af, bf[j], acc[mt][j]);
        }
    }
#pragma unroll
    for (int mt = 0; mt < 2; mt++)
#pragma unroll
        for (int j = 0; j < 2; j++)
            wm::store_matrix_sync(C + mt * 16 * 256 + (w * 2 + j) * 16, acc[mt][j],
                                  256, wm::mem_row_major);
}

// C[32][128] = A[32][K] * W[K][128]; 8 warps (one 16-col tile each), C ld=128.
template <int KT8, int LDA>
__device__ void gemm_tf32_32x128(const float* __restrict__ A,
                                 const float* __restrict__ W,
                                 float* __restrict__ C) {
    int w = threadIdx.x >> 5;
    CFrag acc[2];
#pragma unroll
    for (int mt = 0; mt < 2; mt++) wm::fill_fragment(acc[mt], 0.0f);
    for (int kt = 0; kt < KT8; kt++) {
        BFrag bf;
        wm::load_matrix_sync(bf, W + (size_t)kt * 8 * 128 + w * 16, 128);
#pragma unroll
        for (int i = 0; i < bf.num_elements; i++)
            bf.x[i] = wm::__float_to_tf32(bf.x[i]);
#pragma unroll
        for (int mt = 0; mt < 2; mt++) {
            AFrag af;
            wm::load_matrix_sync(af, A + mt * 16 * LDA + kt * 8, LDA);
#pragma unroll
            for (int i = 0; i < af.num_elements; i++)
                af.x[i] = wm::__float_to_tf32(af.x[i]);
            wm::mma_sync(acc[mt], af, bf, acc[mt]);
        }
    }
#pragma unroll
    for (int mt = 0; mt < 2; mt++)
        wm::store_matrix_sync(C + mt * 16 * 128 + w * 16, acc[mt], 128, wm::mem_row_major);
}

// C16[16][256] = rowpair-max of A[32][K] * W[K][256].
template <int KT8, int LDA>
__device__ void gemm_tf32_32x256_maxpair(const float* __restrict__ A,
                                         const float* __restrict__ W,
                                         float* __restrict__ C16) {
    int w = threadIdx.x >> 5;
    CFrag acc[2][2];
#pragma unroll
    for (int mt = 0; mt < 2; mt++)
#pragma unroll
        for (int j = 0; j < 2; j++) wm::fill_fragment(acc[mt][j], 0.0f);
    for (int kt = 0; kt < KT8; kt++) {
        BFrag bf[2];
#pragma unroll
        for (int j = 0; j < 2; j++) {
            wm::load_matrix_sync(bf[j], W + (size_t)kt * 8 * 256 + (w * 2 + j) * 16, 256);
#pragma unroll
            for (int i = 0; i < bf[j].num_elements; i++)
                bf[j].x[i] = wm::__float_to_tf32(bf[j].x[i]);
        }
#pragma unroll
        for (int mt = 0; mt < 2; mt++) {
            AFrag af;
            wm::load_matrix_sync(af, A + mt * 16 * LDA + kt * 8, LDA);
#pragma unroll
            for (int i = 0; i < af.num_elements; i++)
                af.x[i] = wm::__float_to_tf32(af.x[i]);
#pragma unroll
            for (int j = 0; j < 2; j++)
                wm::mma_sync(acc[mt][j], af, bf[j], acc[mt][j]);
        }
    }
#pragma unroll
    for (int j = 0; j < 2; j++) {
#pragma unroll
        for (int i = 0; i < acc[0][j].num_elements; i++)
            acc[0][j].x[i] = fmaxf(acc[0][j].x[i], acc[1][j].x[i]);
        wm::store_matrix_sync(C16 + (w * 2 + j) * 16, acc[0][j], 256, wm::mem_row_major);
    }
}

// ---------------- prep: blocks 0..7 = FPS over raw xyz; rest = transposes ----------------
struct WT9 {
    const float* W[9];
    int off[9], O[9], K[9], Kpad[9];
};
__global__ void __launch_bounds__(1024) prep_kernel(const float* __restrict__ xyz, WT9 w) {
    __shared__ int   s_far;
    __shared__ float s_v[32];
    __shared__ int   s_i[32];
    int tid = threadIdx.x;
    if (blockIdx.x < B) {
        int b = blockIdx.x;
        const float* base = xyz + (size_t)b * CX * N0;
        float px[8], py[8], pz[8], dist[8];
#pragma unroll
        for (int j = 0; j < 8; j++) {
            int p = tid + j * 1024;
            px[j] = base[p];
            py[j] = base[p + N0];
            pz[j] = base[p + 2 * N0];
            dist[j] = 1e10f;
        }
        float4* out4 = g_l1xyz4 + (size_t)b * S1;
        if (tid == 0) s_far = 0;
        __syncthreads();
        for (int it = 0; it < S1; it++) {
            int far = s_far;
            float cx = base[far], cy = base[far + N0], cz = base[far + 2 * N0];
            if (tid == 0) out4[it] = make_float4(cx, cy, cz, sumsq3(cx, cy, cz));
            float bv = -1.0f; int bj = 0;
#pragma unroll
            for (int j = 0; j < 8; j++) {
                float dx = __fsub_rn(px[j], cx);
                float dy = __fsub_rn(py[j], cy);
                float dz = __fsub_rn(pz[j], cz);
                float d = fmaf(dz, dz, fmaf(dy, dy, __fmul_rn(dx, dx)));
                float nd = fminf(dist[j], d);
                dist[j] = nd;
                if (nd > bv) { bv = nd; bj = j; }
            }
            int bi = tid + bj * 1024;
            warp_argmax(bv, bi);
            if ((tid & 31) == 0) { s_v[tid >> 5] = bv; s_i[tid >> 5] = bi; }
            __syncthreads();
            if (tid < 32) {
                bv = s_v[tid]; bi = s_i[tid];
                warp_argmax(bv, bi);
                if (tid == 0) s_far = bi;
            }
            __syncthreads();
        }
        return;
    }
    int i = (blockIdx.x - B) * 1024 + tid;
    if (i < B * N0) {
        int b = i >> 13, n = i & (N0 - 1);
        const float* src = xyz + (size_t)b * CX * N0 + n;
        float* dst = g_xt + (size_t)i * CX;
        float x = src[0], y = src[(size_t)N0], z = src[(size_t)2 * N0];
#pragma unroll
        for (int c = 0; c < CX; c++) dst[c] = src[(size_t)c * N0];
        g_l0xyz4[i] = make_float4(x, y, z, sumsq3(x, y, z));
        return;
    }
    i -= B * N0;
#pragma unroll
    for (int s = 0; s < 9; s++) {
        int n = w.Kpad[s] * w.O[s];
        if (i < n) {
            int k = i / w.O[s], o = i - k * w.O[s];
            g_wt[w.off[s] + i] = (k < w.K[s]) ? w.W[s][o * w.K[s] + k] : 0.0f;
            return;
        }
        i -= n;
    }
}

// ---------------- FPS body (float4 source) ----------------
template <int PPT, int NP>
__device__ __forceinline__ void fps_body4(const float4* __restrict__ base,
                                          float4* __restrict__ out4,
                                          int tid, int* s_far, float* s_v, int* s_i) {
    float px[PPT], py[PPT], pz[PPT], dist[PPT];
#pragma unroll
    for (int j = 0; j < PPT; j++) {
        float4 P = base[tid + j * 1024];
        px[j] = P.x; py[j] = P.y; pz[j] = P.z;
        dist[j] = 1e10f;
    }
    if (tid == 0) *s_far = 0;
    __syncthreads();
    for (int it = 0; it < NP; it++) {
        int far = *s_far;
        float4 C = base[far];
        float cx = C.x, cy = C.y, cz = C.z;
        if (tid == 0) out4[it] = make_float4(cx, cy, cz, sumsq3(cx, cy, cz));
        float bv = -1.0f; int bj = 0;
#pragma unroll
        for (int j = 0; j < PPT; j++) {
            float dx = __fsub_rn(px[j], cx);
            float dy = __fsub_rn(py[j], cy);
            float dz = __fsub_rn(pz[j], cz);
            float d = fmaf(dz, dz, fmaf(dy, dy, __fmul_rn(dx, dx)));
            float nd = fminf(dist[j], d);
            dist[j] = nd;
            if (nd > bv) { bv = nd; bj = j; }
        }
        int bi = tid + bj * 1024;
        warp_argmax(bv, bi);
        if ((tid & 31) == 0) { s_v[tid >> 5] = bv; s_i[tid >> 5] = bi; }
        __syncthreads();
        if (tid < 32) {
            bv = s_v[tid]; bi = s_i[tid];
            warp_argmax(bv, bi);
            if (tid == 0) *s_far = bi;
        }
        __syncthreads();
    }
}

// ---------------- warp ball-query body ----------------
__device__ __forceinline__ void ball_body(const float4* __restrict__ centers,
                                          const float4* __restrict__ pts4,
                                          int nptsB, int SQ, float r2, int nsample,
                                          int* __restrict__ out, int gw, int lane,
                                          int* __restrict__ buf) {
    int b = gw / SQ;
    float4 C = centers[gw];
    float cx = C.x, cy = C.y, cz = C.z, sc = C.w;
    const float4* pb = pts4 + (size_t)b * nptsB;
    int kept = 0;
    for (int j0 = 0; j0 < nptsB; j0 += 32) {
        int p = j0 + lane;
        float4 P = pb[p];
        float d = sqdist_pre(sc, cx, cy, cz, P.x, P.y, P.z, P.w);
        bool in = !(d > r2);
        unsigned m = __ballot_sync(0xffffffffu, in);
        int rank = kept + __popc(m & ((1u << lane) - 1u));
        if (in && rank < nsample) buf[rank] = p;
        kept += __popc(m);
        if (kept >= nsample) break;
    }
    __syncwarp();
    int first = buf[0];
    for (int i = lane; i < nsample; i += 32)
        out[(size_t)gw * nsample + i] = (i < kept) ? buf[i] : first;
}

// ---------------- warp 3-NN body ----------------
__device__ __forceinline__ void nn3_body(const float4* __restrict__ qpts4,
                                         const float4* __restrict__ pts4,
                                         int nptsB, int SQ,
                                         int* __restrict__ oi, float* __restrict__ ow,
                                         int gw, int lane) {
    int b = gw / SQ;
    float4 Q = qpts4[gw];
    float cx = Q.x, cy = Q.y, cz = Q.z, sc = Q.w;
    const float4* pb = pts4 + (size_t)b * nptsB;
    float D0 = FLT_MAX, D1 = FLT_MAX, D2 = FLT_MAX;
    int   I0 = 0x7fffffff, I1 = 0x7fffffff, I2 = 0x7fffffff;
    for (int p = lane; p < nptsB; p += 32) {
        float4 P = pb[p];
        float d = sqdist_pre(sc, cx, cy, cz, P.x, P.y, P.z, P.w);
        top3_insert(d, p, D0, D1, D2, I0, I1, I2);
    }
    for (int off = 16; off; off >>= 1) {
        float e0 = __shfl_down_sync(0xffffffffu, D0, off);
        float e1 = __shfl_down_sync(0xffffffffu, D1, off);
        float e2 = __shfl_down_sync(0xffffffffu, D2, off);
        int   f0 = __shfl_down_sync(0xffffffffu, I0, off);
        int   f1 = __shfl_down_sync(0xffffffffu, I1, off);
        int   f2 = __shfl_down_sync(0xffffffffu, I2, off);
        top3_insert(e0, f0, D0, D1, D2, I0, I1, I2);
        top3_insert(e1, f1, D0, D1, D2, I0, I1, I2);
        top3_insert(e2, f2, D0, D1, D2, I0, I1, I2);
    }
    if (lane == 0) {
        float r0 = 1.0f / (D0 + 1e-8f);
        float r1 = 1.0f / (D1 + 1e-8f);
        float r2 = 1.0f / (D2 + 1e-8f);
        float s = (r0 + r1) + r2;
        oi[(size_t)gw * 3 + 0] = I0; oi[(size_t)gw * 3 + 1] = I1; oi[(size_t)gw * 3 + 2] = I2;
        ow[(size_t)gw * 3 + 0] = r0 / s; ow[(size_t)gw * 3 + 1] = r1 / s; ow[(size_t)gw * 3 + 2] = r2 / s;
    }
}

// ---------------- M1: fps1 (0..7) + ball1 (8..263) + nn1 (264..2311) ----------------
constexpr int M1_BALL1 = 256;
constexpr int M1_NN1   = 2048;
constexpr int M1_GRID  = B + M1_BALL1 + M1_NN1;

__global__ void __launch_bounds__(1024) m1_kernel(float r2_1) {
    __shared__ int   sbuf[32][32];
    __shared__ int   s_far;
    __shared__ float s_v[32];
    __shared__ int   s_i[32];
    if (blockIdx.x < B) {
        fps_body4<1, S2>(g_l1xyz4 + (size_t)blockIdx.x * S1,
                         g_l2xyz4 + (size_t)blockIdx.x * S2,
                         threadIdx.x, &s_far, s_v, s_i);
    } else if (blockIdx.x < B + M1_BALL1) {
        int wl = threadIdx.x >> 5, lane = threadIdx.x & 31;
        int gw = (blockIdx.x - B) * 32 + wl;
        ball_body(g_l1xyz4, g_l0xyz4, N0, S1, r2_1, K1, g_ball1, gw, lane, &sbuf[wl][0]);
    } else {
        int wl = threadIdx.x >> 5, lane = threadIdx.x & 31;
        int gw = (blockIdx.x - B - M1_BALL1) * 32 + wl;
        nn3_body(g_l0xyz4, g_l1xyz4, S1, N0, g_nn1i, g_nn1w, gw, lane);
    }
}

// ---------------- M2: sa1 (2 queries/block, 128 thr) + ball2 + nn2 ----------------
constexpr int M2_SA1   = 4096;   // 8192 queries / 2
constexpr int M2_BALL2 = 1024;   // 4096 queries / 4 warps
constexpr int M2_NN2   = 2048;   // 8192 queries / 4 warps
constexpr int M2_GRID  = M2_SA1 + M2_BALL2 + M2_NN2;

__global__ void __launch_bounds__(128) m2_kernel(const float* __restrict__ b0,
                                                 const float* __restrict__ b1,
                                                 const float* __restrict__ b2,
                                                 float r2_2) {
    __shared__ __align__(16) float g  [32][28];
    __shared__ __align__(16) float h1s[32][64];
    __shared__ __align__(16) float h2s[32][128];
    __shared__ __align__(16) float pmax[4][128];
    __shared__ int   sidx[32];
    __shared__ float ctr[2][4];
    __shared__ int   sbuf[4][32];
    int bid = blockIdx.x;
    int tid = threadIdx.x;
    int wl = tid >> 5, lane = tid & 31;

    if (bid >= M2_SA1) {
        int r = bid - M2_SA1;
        if (r < M2_BALL2) {
            int gw = r * 4 + wl;
            ball_body(g_l2xyz4, g_l1xyz4, S1, S2, r2_2, K2, g_ball2, gw, lane, &sbuf[wl][0]);
        } else {
            int gw = (r - M2_BALL2) * 4 + wl;
            nn3_body(g_l1xyz4, g_l2xyz4, S2, S1, g_nn2i, g_nn2w, gw, lane);
        }
        return;
    }

    int q0 = bid * 2;
    int b = q0 >> 10;
    if (tid < 32) sidx[tid] = g_ball1[q0 * 16 + tid];
    if (tid >= 32 && tid < 40) ((float*)ctr)[tid - 32] = ((const float*)&g_l1xyz4[q0])[tid - 32];
    __syncthreads();
    for (int e = tid; e < 32 * 28; e += 128) {
        int r = e / 28, c = e - r * 28;
        float v = 0.0f;
        if (c < 27) {
            const float* row = g_xt + ((size_t)(b * N0 + sidx[r])) * CX;
            v = (c < 3) ? (row[c] - ctr[r >> 4][c]) : row[c - 3];
        }
        g[r][c] = v;
    }
    __syncthreads();
    {   // layer1: K=28, O=64
        int og = tid & 15, rg = tid >> 4, o0 = og * 4;
        float acc[4][4];
#pragma unroll
        for (int r = 0; r < 4; r++)
#pragma unroll
            for (int j = 0; j < 4; j++) acc[r][j] = b0[o0 + j];
        mm4<4>(g_wt + OFF_SA1_0, 64, og, 28, &g[rg * 4][0], 28, acc);
#pragma unroll
        for (int r = 0; r < 4; r++)
#pragma unroll
            for (int j = 0; j < 4; j++) h1s[rg * 4 + r][o0 + j] = fmaxf(acc[r][j], 0.0f);
    }
    __syncthreads();
    {   // layer2: K=64, O=128
        int og = tid & 31, rg = tid >> 5, o0 = og * 4;
        float acc[8][4];
#pragma unroll
        for (int r = 0; r < 8; r++)
#pragma unroll
            for (int j = 0; j < 4; j++) acc[r][j] = b1[o0 + j];
        mm4<8>(g_wt + OFF_SA1_1, 128, og, 64, &h1s[rg * 8][0], 64, acc);
#pragma unroll
        for (int r = 0; r < 8; r++)
#pragma unroll
            for (int j = 0; j < 4; j++) h2s[rg * 8 + r][o0 + j] = fmaxf(acc[r][j], 0.0f);
    }
    __syncthreads();
    {   // layer3: K=128, O=128, partial max
        int og = tid & 31, rg = tid >> 5, o0 = og * 4;
        float acc[8][4];
#pragma unroll
        for (int r = 0; r < 8; r++)
#pragma unroll
            for (int j = 0; j < 4; j++) acc[r][j] = 0.0f;
        mm4<8>(g_wt + OFF_SA1_2, 128, og, 128, &h2s[rg * 8][0], 128, acc);
#pragma unroll
        for (int j = 0; j < 4; j++) {
            float m = acc[0][j];
#pragma unroll
            for (int r = 1; r < 8; r++) m = fmaxf(m, acc[r][j]);
            pmax[rg][o0 + j] = m;
        }
    }
    __syncthreads();
    {
        int o = tid;
        float m0 = fmaxf(pmax[0][o], pmax[1][o]);
        float m1 = fmaxf(pmax[2][o], pmax[3][o]);
        g_l1p[(size_t)q0 * 128 + o]       = fmaxf(m0 + b2[o], 0.0f);
        g_l1p[(size_t)(q0 + 1) * 128 + o] = fmaxf(m1 + b2[o], 0.0f);
    }
}

// ---------------- SA2 (wmma tf32): 256 threads, c16 aliased onto g ----------------
constexpr int SA2_SMEM = (32 * 136 + 32 * 128) * 4;   // 33792 B (c16 aliases g)

__global__ void __launch_bounds__(256, 4) sa2_kernel(const float* __restrict__ b0,
                                                     const float* __restrict__ b1) {
    extern __shared__ float sd[];
    float* g   = sd;                 // [32][136] (cols 131..135 zero)
    float* h1s = sd + 32 * 136;      // [32][128]
    float* c16 = sd;                 // [16][256] aliases g (g dead after layer1 gemm)
    __shared__ int   sidx[32];
    __shared__ float ctr[3];
    int tid = threadIdx.x;

    int q = blockIdx.x;
    int b = q >> 9;
    if (tid < 32) sidx[tid] = g_ball2[q * 32 + tid];
    if (tid >= 32 && tid < 35) ctr[tid - 32] = ((const float*)&g_l2xyz4[q])[tid - 32];
    __syncthreads();
    for (int e = tid; e < 32 * 136; e += 256) {
        int r = e / 136, c = e - r * 136;
        float v = 0.0f;
        if (c < 131) {
            int p = sidx[r];
            if (c < 3) v = ((const float*)&g_l1xyz4[(size_t)b * S1 + p])[c] - ctr[c];
            else       v = g_l1p[((size_t)b * S1 + p) * 128 + (c - 3)];
        }
        g[r * 136 + c] = v;
    }
    __syncthreads();
    gemm_tf32_32x128<17, 136>(g, g_wt + OFF_SA2_0, h1s);
    __syncthreads();
    for (int e = tid; e < 32 * 128; e += 256)
        h1s[e] = fmaxf(h1s[e] + b0[e & 127], 0.0f);
    __syncthreads();   // g fully dead after this point; c16 may now overwrite it
    gemm_tf32_32x256_maxpair<16, 128>(h1s, g_wt + OFF_SA2_1, c16);
    __syncthreads();
    {
        int o = tid;
        float m = c16[o];
#pragma unroll
        for (int r = 1; r < 16; r++) m = fmaxf(m, c16[r * 256 + o]);
        g_l2p[(size_t)q * 256 + o] = fmaxf(m + b1[o], 0.0f);
    }
}

// ---------------- FP2 (wmma tf32): interp + concat + MLP(384->256->256), 32 rows ----------------
constexpr int FP2_SMEM = (32 * 384 + 32 * 256) * 4;   // 81920 B

__global__ void __launch_bounds__(256) fp2_kernel(const float* __restrict__ b0,
                                                  const float* __restrict__ b1) {
    extern __shared__ float sd[];
    float* feat = sd;               // [32][384]
    float* h1s  = sd + 32 * 384;    // [32][256]
    __shared__ int   nni[32][3];
    __shared__ float nnw[32][3];
    int row0 = blockIdx.x * 32;
    int b = row0 >> 10;
    int tid = threadIdx.x;
    if (tid < 96)                    nni[tid / 3][tid % 3] = g_nn2i[(size_t)row0 * 3 + tid];
    else if (tid < 192) { int t = tid - 96; nnw[t / 3][t % 3] = g_nn2w[(size_t)row0 * 3 + t]; }
    for (int e = tid; e < 32 * 128; e += 256) {
        int r = e >> 7, c = e & 127;
        feat[r * 384 + c] = g_l1p[((size_t)row0 + r) * 128 + c];
    }
    __syncthreads();
    {
        const float* p2 = g_l2p + (size_t)b * S2 * 256;
        int c = tid;
#pragma unroll 4
        for (int r = 0; r < 32; r++) {
            float v = p2[(size_t)nni[r][0] * 256 + c] * nnw[r][0];
            v += p2[(size_t)nni[r][1] * 256 + c] * nnw[r][1];
            v += p2[(size_t)nni[r][2] * 256 + c] * nnw[r][2];
            feat[r * 384 + 128 + c] = v;
        }
    }
    __syncthreads();
    gemm_tf32_1p<48, 384>(feat, g_wt + OFF_FP2_0, h1s);
    __syncthreads();
    for (int e = tid; e < 32 * 256; e += 256)
        h1s[e] = fmaxf(h1s[e] + b0[e & 255], 0.0f);
    __syncthreads();
    gemm_tf32_1p<32, 256>(h1s, g_wt + OFF_FP2_1, feat);   // staging (ld 256)
    __syncthreads();
    for (int e = tid; e < 32 * 256; e += 256)
        g_l1p2[((size_t)row0 + (e >> 8)) * 256 + (e & 255)] = fmaxf(feat[e] + b1[e & 255], 0.0f);
}

// ---------------- FP1 (wmma tf32): concat + MLP(288pad->256->256) -> out ----------------
constexpr int FP1_SMEM = (32 * 288 + 32 * 256) * 4;

__global__ void __launch_bounds__(256) fp1_kernel(const float* __restrict__ b0,
                                                  const float* __restrict__ b1,
                                                  float* __restrict__ out) {
    extern __shared__ float sd[];
    float* feat = sd;               // [32][288], cols 283..287 zero
    float* h1s  = sd + 32 * 288;    // [32][256]
    __shared__ int   nni[32][3];
    __shared__ float nnw[32][3];
    int row0 = blockIdx.x * 32;
    int b = row0 >> 13;
    int tid = threadIdx.x;
    if (tid < 96)                    nni[tid / 3][tid % 3] = g_nn1i[(size_t)row0 * 3 + tid];
    else if (tid < 192) { int t = tid - 96; nnw[t / 3][t % 3] = g_nn1w[(size_t)row0 * 3 + t]; }
    for (int e = tid; e < 32 * 27; e += 256) {
        int r = e / 27, c = e - r * 27;
        const float* row = g_xt + (size_t)(row0 + r) * CX;
        feat[r * 288 + c] = (c < 3) ? row[c] : row[c - 3];
    }
    if (tid < 32) {
#pragma unroll
        for (int c = 283; c < 288; c++) feat[tid * 288 + c] = 0.0f;
    }
    __syncthreads();
    {
        const float* p1 = g_l1p2 + (size_t)b * S1 * 256;
        int c = tid;
#pragma unroll 4
        for (int r = 0; r < 32; r++) {
            float v = p1[(size_t)nni[r][0] * 256 + c] * nnw[r][0];
            v += p1[(size_t)nni[r][1] * 256 + c] * nnw[r][1];
            v += p1[(size_t)nni[r][2] * 256 + c] * nnw[r][2];
            feat[r * 288 + 27 + c] = v;
        }
    }
    __syncthreads();
    gemm_tf32_1p<36, 288>(feat, g_wt + OFF_FP1_0, h1s);
    __syncthreads();
    for (int e = tid; e < 32 * 256; e += 256)
        h1s[e] = fmaxf(h1s[e] + b0[e & 255], 0.0f);
    __syncthreads();
    gemm_tf32_1p<32, 256>(h1s, g_wt + OFF_FP1_1, feat);   // staging (ld 256)
    __syncthreads();
    for (int e = tid; e < 32 * 256; e += 256)
        out[((size_t)row0 + (e >> 8)) * 256 + (e & 255)] = fmaxf(feat[e] + b1[e & 255], 0.0f);
}

// ---------------- launch ----------------
extern "C" void kernel_launch(void* const* d_in, const int* in_sizes, int n_in,
                              void* d_out, int out_size) {
    const float* xyz = (const float*)d_in[0];
    const float* sa1_b0 = (const float*)d_in[2];
    const float* sa1_b1 = (const float*)d_in[4];
    const float* sa1_b2 = (const float*)d_in[6];
    const float* sa2_b0 = (const float*)d_in[8];
    const float* sa2_b1 = (const float*)d_in[10];
    const float* fp2_b0 = (const float*)d_in[12];
    const float* fp2_b1 = (const float*)d_in[14];
    const float* fp1_b0 = (const float*)d_in[16];
    const float* fp1_b1 = (const float*)d_in[18];
    float* out = (float*)d_out;

    const float r2_1 = (float)(0.035 * 0.035);
    const float r2_2 = (float)(0.0176 * 0.0176);

    WT9 w;
    const int offs[9]  = { OFF_SA1_0, OFF_SA1_1, OFF_SA1_2, OFF_SA2_0, OFF_SA2_1,
                           OFF_FP2_0, OFF_FP2_1, OFF_FP1_0, OFF_FP1_1 };
    const int Os[9]    = { 64, 128, 128, 128, 256, 256, 256, 256, 256 };
    const int Ks[9]    = { 27, 64, 128, 131, 128, 384, 256, 283, 256 };
    const int Kpads[9] = { 28, 64, 128, 136, 128, 384, 256, 288, 256 };
    const int widx[9]  = { 1, 3, 5, 7, 9, 11, 13, 15, 17 };
    for (int i = 0; i < 9; i++) {
        w.W[i] = (const float*)d_in[widx[i]];
        w.off[i] = offs[i]; w.O[i] = Os[i]; w.K[i] = Ks[i]; w.Kpad[i] = Kpads[i];
    }
    int prep_grid = B + (B * N0 + TOTAL_W + 1023) / 1024;
    prep_kernel<<<prep_grid, 1024>>>(xyz, w);

    m1_kernel<<<M1_GRID, 1024>>>(r2_1);
    m2_kernel<<<M2_GRID, 128>>>(sa1_b0, sa1_b1, sa1_b2, r2_2);

    cudaFuncSetAttribute(sa2_kernel, cudaFuncAttributeMaxDynamicSharedMemorySize, SA2_SMEM);
    sa2_kernel<<<B * S2, 256, SA2_SMEM>>>(sa2_b0, sa2_b1);

    cudaFuncSetAttribute(fp2_kernel, cudaFuncAttributeMaxDynamicSharedMemorySize, FP2_SMEM);
    fp2_kernel<<<B * S1 / 32, 256, FP2_SMEM>>>(fp2_b0, fp2_b1);

    cudaFuncSetAttribute(fp1_kernel, cudaFuncAttributeMaxDynamicSharedMemorySize, FP1_SMEM);
    fp1_kernel<<<B * N0 / 32, 256, FP1_SMEM>>>(fp1_b0, fp1_b1, out);
}